// round 14
// baseline (speedup 1.0000x reference)
#include <cuda_runtime.h>
#include <cuda_fp16.h>
#include <cuda_bf16.h>
#include <math_constants.h>
#include <cstdint>

#define KC     200
#define NT     26            // n-tiles of 8 -> KPAD = 208
#define KPAD   (NT * 8)
#define TILE_M 128
#define SMAX   60000
#define APITCH 72            // fp16 elems per smem row (144B, conflict-free)
#define NTS    25            // uint4 per Qc row (200 fp16)
#define TRP    101           // u32 pitch of transpose buffer (conflict-dodging)
#define QSCALE 64.0f         // fp16 storage scale; product scale = 4096
#define QINV   (1.0f / 4096.0f)

// ---------------- scratch ----------------------------------------------------
__device__ __align__(16) __half g_Qh[(size_t)SMAX * KC + 8];

// ---------------- helpers ----------------------------------------------------
__device__ __forceinline__ uint32_t pack_h2(float a, float b) {
    __half2 t = __floats2half2_rn(a, b);   // a = low half
    return *(uint32_t*)&t;
}

__device__ __forceinline__ void mma_f16(float c[4], const uint32_t a[4],
                                        uint32_t b0, uint32_t b1) {
    asm volatile(
        "mma.sync.aligned.m16n8k16.row.col.f32.f16.f16.f32 "
        "{%0,%1,%2,%3}, {%4,%5,%6,%7}, {%8,%9}, {%0,%1,%2,%3};"
        : "+f"(c[0]), "+f"(c[1]), "+f"(c[2]), "+f"(c[3])
        : "r"(a[0]), "r"(a[1]), "r"(a[2]), "r"(a[3]), "r"(b0), "r"(b1));
}

__device__ __forceinline__ void ldsm_x4(uint32_t& r0, uint32_t& r1,
                                        uint32_t& r2, uint32_t& r3,
                                        uint32_t addr) {
    asm volatile("ldmatrix.sync.aligned.m8n8.x4.shared.b16 {%0,%1,%2,%3}, [%4];"
        : "=r"(r0), "=r"(r1), "=r"(r2), "=r"(r3) : "r"(addr));
}

// ---------------- K1: fused fp16-HMMA logits + softmax + point + Qc ----------
// pool holds Ah[128][72] (18432B) + Bh[208][72] (29952B) = 48384B,
// later reused as tr[128][101] u32 = 51712B.
#define POOL_SZ 51712

__global__ void __launch_bounds__(256) k1_fused(
    const float* __restrict__ Z, const float* __restrict__ S,
    const float* __restrict__ sel_mu, const float* __restrict__ spa_mu,
    float* __restrict__ out, int s, float cpoint)
{
    __shared__ float4 cfp[KPAD];                 // (p0,p1,p2, 0.5*||mu||^2)
    __shared__ float4 rcp[TILE_M];               // (s0,s1,s2, ||x||^2)
    __shared__ __align__(16) char pool[POOL_SZ]; // Ah+Bh, later tr

    __half* Ah = (__half*)pool;                          // [TILE_M][APITCH]
    __half* Bh = (__half*)(pool + TILE_M * APITCH * 2);  // [KPAD][APITCH]

    const int tid = threadIdx.x, lane = tid & 31, w = tid >> 5;
    const int g = lane >> 2, tg = lane & 3;
    const int i0 = blockIdx.x * TILE_M;

    // ---- stage B (sel_mu) as fp16 ----
    #pragma unroll
    for (int it = 0; it < (KPAD * 16) / 256; ++it) {
        const int idx = it * 256 + tid;
        const int row = idx >> 4, j4 = idx & 15;
        float4 v = make_float4(0.f, 0.f, 0.f, 0.f);
        if (row < KC) v = ((const float4*)sel_mu)[row * 16 + j4];
        uint32_t* dh = (uint32_t*)(Bh + row * APITCH + j4 * 4);
        dh[0] = pack_h2(v.x, v.y); dh[1] = pack_h2(v.z, v.w);
    }

    // ---- stage A (Z tile) as fp16 ----
    #pragma unroll
    for (int it = 0; it < (TILE_M * 16) / 256; ++it) {
        const int idx = it * 256 + tid;
        const int row = idx >> 4, j4 = idx & 15;
        const int gi = i0 + row;
        float4 v = make_float4(0.f, 0.f, 0.f, 0.f);
        if (gi < s) v = ((const float4*)Z)[(size_t)gi * 16 + j4];
        uint32_t* dh = (uint32_t*)(Ah + row * APITCH + j4 * 4);
        dh[0] = pack_h2(v.x, v.y); dh[1] = pack_h2(v.z, v.w);
    }

    // ---- per-cluster coefficients ----
    if (tid < KPAD) {
        const int k = tid;
        float4 cf = make_float4(0.f, 0.f, 0.f, 1e30f);
        if (k < KC) {
            const float a = spa_mu[3 * k], b = spa_mu[3 * k + 1], c = spa_mu[3 * k + 2];
            float mn = a * a + b * b + c * c;
            const float4* mr = (const float4*)sel_mu + (size_t)k * 16;
            #pragma unroll
            for (int j = 0; j < 16; ++j) {
                float4 m = mr[j];
                mn += m.x * m.x + m.y * m.y + m.z * m.z + m.w * m.w;
            }
            cf = make_float4(a, b, c, 0.5f * mn);
        }
        cfp[k] = cf;
    }

    // ---- per-row constants ----
    if (tid < TILE_M) {
        const int gi = i0 + tid;
        float4 rc = make_float4(0.f, 0.f, 0.f, 0.f);
        if (gi < s) {
            float zn = 0.f;
            const float4* zr = (const float4*)Z + (size_t)gi * 16;
            #pragma unroll
            for (int j = 0; j < 16; ++j) {
                float4 z = zr[j];
                zn += z.x * z.x + z.y * z.y + z.z * z.z + z.w * z.w;
            }
            rc.x = S[(size_t)3 * gi];
            rc.y = S[(size_t)3 * gi + 1];
            rc.z = S[(size_t)3 * gi + 2];
            rc.w = zn + rc.x * rc.x + rc.y * rc.y + rc.z * rc.z;
        }
        rcp[tid] = rc;
    }
    __syncthreads();

    // ---- MMA mainloop: warp owns rows w*16..w*16+15, all 26 tiles ----
    float acc[NT][4];
    #pragma unroll
    for (int t = 0; t < NT; ++t)
        acc[t][0] = acc[t][1] = acc[t][2] = acc[t][3] = 0.f;

    const int r0 = w * 16 + g;
    {
        const int rr = lane & 7, q = lane >> 3;
        const uint32_t AhS = (uint32_t)__cvta_generic_to_shared(Ah);
        const uint32_t BhS = (uint32_t)__cvta_generic_to_shared(Bh);
        const uint32_t aAddr = AhS
            + (uint32_t)((w * 16 + (q & 1) * 8 + rr) * (APITCH * 2))
            + (uint32_t)((q >> 1) * 16);
        const uint32_t bAddr = BhS
            + (uint32_t)(((q >> 1) * 8 + rr) * (APITCH * 2))
            + (uint32_t)((q & 1) * 16);

        #pragma unroll
        for (int ks = 0; ks < 4; ++ks) {
            const uint32_t kb = ks * 32;   // 16 fp16 = 32 bytes per k-step
            uint32_t a[4];
            ldsm_x4(a[0], a[1], a[2], a[3], aAddr + kb);
            #pragma unroll
            for (int u = 0; u < 13; ++u) {
                uint32_t b0, b1, b2, b3;
                ldsm_x4(b0, b1, b2, b3,
                        bAddr + (uint32_t)(u * (16 * APITCH * 2)) + kb);
                mma_f16(acc[2 * u],     a, b0, b1);
                mma_f16(acc[2 * u + 1], a, b2, b3);
            }
        }
    }

    // ---- epilogue: logits + full-warp softmax (rows r0, r0+8) ----
    const float4 rc0 = rcp[r0];
    const float4 rc1 = rcp[r0 + 8];

    float m0 = -CUDART_INF_F, m1 = -CUDART_INF_F;
    #pragma unroll
    for (int t = 0; t < NT; ++t) {
        const int cb = t * 8 + 2 * tg;
        const float4 c0 = cfp[cb];
        const float4 c1 = cfp[cb + 1];
        acc[t][0] += rc0.x * c0.x + rc0.y * c0.y + rc0.z * c0.z - c0.w;
        acc[t][1] += rc0.x * c1.x + rc0.y * c1.y + rc0.z * c1.z - c1.w;
        acc[t][2] += rc1.x * c0.x + rc1.y * c0.y + rc1.z * c0.z - c0.w;
        acc[t][3] += rc1.x * c1.x + rc1.y * c1.y + rc1.z * c1.z - c1.w;
        m0 = fmaxf(m0, fmaxf(acc[t][0], acc[t][1]));
        m1 = fmaxf(m1, fmaxf(acc[t][2], acc[t][3]));
    }
    m0 = fmaxf(m0, __shfl_xor_sync(0xffffffffu, m0, 1));
    m0 = fmaxf(m0, __shfl_xor_sync(0xffffffffu, m0, 2));
    m1 = fmaxf(m1, __shfl_xor_sync(0xffffffffu, m1, 1));
    m1 = fmaxf(m1, __shfl_xor_sync(0xffffffffu, m1, 2));

    float se0 = 0.f, sl0 = 0.f, se1 = 0.f, sl1 = 0.f;
    #pragma unroll
    for (int t = 0; t < NT; ++t) {
        float e;
        e = __expf(acc[t][0] - m0); se0 += e; sl0 += e * acc[t][0]; acc[t][0] = e;
        e = __expf(acc[t][1] - m0); se0 += e; sl0 += e * acc[t][1]; acc[t][1] = e;
        e = __expf(acc[t][2] - m1); se1 += e; sl1 += e * acc[t][2]; acc[t][2] = e;
        e = __expf(acc[t][3] - m1); se1 += e; sl1 += e * acc[t][3]; acc[t][3] = e;
    }
    se0 += __shfl_xor_sync(0xffffffffu, se0, 1);
    se0 += __shfl_xor_sync(0xffffffffu, se0, 2);
    sl0 += __shfl_xor_sync(0xffffffffu, sl0, 1);
    sl0 += __shfl_xor_sync(0xffffffffu, sl0, 2);
    se1 += __shfl_xor_sync(0xffffffffu, se1, 1);
    se1 += __shfl_xor_sync(0xffffffffu, se1, 2);
    sl1 += __shfl_xor_sync(0xffffffffu, sl1, 1);
    sl1 += __shfl_xor_sync(0xffffffffu, sl1, 2);

    const float inv0 = 1.0f / se0, inv1 = 1.0f / se1;
    const int gr0 = i0 + r0, gr1 = gr0 + 8;
    if (tg == 0) {
        if (gr0 < s) out[gr0] = 0.5f * rc0.w + cpoint - sl0 * inv0;
        if (gr1 < s) out[gr1] = 0.5f * rc1.w + cpoint - sl1 * inv1;
    }

    __syncthreads();    // all ldsm reads done -> pool reusable as tr

    // ---- clipped Q*64 -> fp16, smem transpose buffer (rows r0, r0+8) ----
    uint32_t* tr = (uint32_t*)pool;              // [TILE_M][TRP] u32 (fp16x2)
    #pragma unroll
    for (int t = 0; t < NTS; ++t) {              // tiles 0..24 (cols < 200)
        const int c = 4 * t + tg;                // u32 column 0..99
        float qa = fminf(fmaxf(acc[t][0] * inv0, 1e-6f), 1.0f - 1e-6f) * QSCALE;
        float qb = fminf(fmaxf(acc[t][1] * inv0, 1e-6f), 1.0f - 1e-6f) * QSCALE;
        float qc = fminf(fmaxf(acc[t][2] * inv1, 1e-6f), 1.0f - 1e-6f) * QSCALE;
        float qd = fminf(fmaxf(acc[t][3] * inv1, 1e-6f), 1.0f - 1e-6f) * QSCALE;
        tr[r0 * TRP + c]       = pack_h2(qa, qb);
        tr[(r0 + 8) * TRP + c] = pack_h2(qc, qd);
    }
    __syncthreads();

    // ---- coalesced store: each warp writes 16 full rows ----
    {
        uint32_t* __restrict__ qg = (uint32_t*)g_Qh;   // 100 u32 per row
        #pragma unroll
        for (int rr = 0; rr < 16; ++rr) {
            const int row = w * 16 + rr;
            const int gr = i0 + row;
            if (gr >= s) break;
            const uint32_t* src = tr + row * TRP;
            uint32_t* dst = qg + (size_t)gr * 100;
            dst[lane]      = src[lane];
            dst[lane + 32] = src[lane + 32];
            dst[lane + 64] = src[lane + 64];
            if (lane < 4) dst[lane + 96] = src[lane + 96];
        }
    }
}

// ---------------- K2: doublet energy (warp/point, fp16 HFMA2 dot) ------------
__global__ void __launch_bounds__(256) k2_doublet(float* __restrict__ out,
                                                  const void* __restrict__ Dv,
                                                  int s, int n)
{
    const int t = threadIdx.x, lane = t & 31, w = t >> 5;

    // dtype probe: true int64 ids are all in [0, s); int32 data read as int64
    // packs two ids -> almost surely out of range somewhere in 32 words.
    const long long probe = ((const long long*)Dv)[lane];
    const bool ok = (probe >= 0) && (probe < (long long)s);
    const bool is64 = (__ballot_sync(0xffffffffu, ok) == 0xffffffffu);

    const int i = blockIdx.x * 8 + w;
    if (i >= s) return;

    const uint4* __restrict__ Q4 = (const uint4*)g_Qh;  // row = 25 uint4
    const uint4 zero4 = make_uint4(0, 0, 0, 0);
    const unsigned ubase = (unsigned)i * NTS + (unsigned)lane;
    const uint4 ov = (lane < NTS) ? Q4[ubase] : zero4;
    const __half2* o2 = (const __half2*)&ov;            // 4 half2

    float doublet = 0.f;
    for (int base = 0; base < n; base += 6) {
        __half2 acch[6]; int val[6];
        #pragma unroll
        for (int nb = 0; nb < 6; ++nb) {
            acch[nb] = __floats2half2_rn(0.f, 0.f); val[nb] = 0;
            const int q = base + nb;
            if (q < n) {
                long long d = is64 ? ((const long long*)Dv)[(unsigned)i * n + q]
                                   : (long long)((const int*)Dv)[(unsigned)i * n + q];
                val[nb] = (d >= 0 && d < s) ? 1 : 0;
                const unsigned ridx = (unsigned)(val[nb] ? (int)d : i) * NTS
                                    + (unsigned)lane;
                const uint4 nv = (lane < NTS) ? Q4[ridx] : zero4;
                const __half2* n2 = (const __half2*)&nv;
                __half2 a = __hmul2(o2[0], n2[0]);
                a = __hfma2(o2[1], n2[1], a);
                a = __hfma2(o2[2], n2[2], a);
                a = __hfma2(o2[3], n2[3], a);
                acch[nb] = a;
            }
        }
        #pragma unroll
        for (int off = 16; off; off >>= 1) {
            #pragma unroll
            for (int nb = 0; nb < 6; ++nb) {
                uint32_t u = __shfl_xor_sync(0xffffffffu,
                                             *(const uint32_t*)&acch[nb], off);
                acch[nb] = __hadd2(acch[nb], *(const __half2*)&u);
            }
        }
        float co[6];
        #pragma unroll
        for (int nb = 0; nb < 6; ++nb) {
            const float2 f = __half22float2(acch[nb]);
            co[nb] = val[nb] ? (f.x + f.y) * QINV : 1.0f;
        }
        doublet -= __logf(co[0] * co[1]) + __logf(co[2] * co[3])
                 + __logf(co[4] * co[5]);
    }
    if (lane == 0) out[i] += doublet;
}

// ---------------- launch -----------------------------------------------------
extern "C" void kernel_launch(void* const* d_in, const int* in_sizes, int n_in,
                              void* d_out, int out_size)
{
    const float* Z      = (const float*)d_in[0];
    const float* S      = (const float*)d_in[1];
    const void*  D      = d_in[2];
    const float* sel_mu = (const float*)d_in[3];
    const float* spa_mu = (const float*)d_in[4];
    float* out = (float*)d_out;

    const int s  = in_sizes[1] / 3;
    const int dz = in_sizes[0] / s;
    const int n  = in_sizes[2] / s;
    const float cpoint = 0.5f * (float)(dz + 3) * 1.8378770664093453f;

    k1_fused<<<(s + TILE_M - 1) / TILE_M, 256>>>(
        Z, S, sel_mu, spa_mu, out, s, cpoint);
    k2_doublet<<<(s + 7) / 8, 256>>>(out, D, s, n);
}

// round 15
// speedup vs baseline: 1.4525x; 1.4525x over previous
#include <cuda_runtime.h>
#include <cuda_fp16.h>
#include <cuda_bf16.h>
#include <math_constants.h>
#include <cstdint>

#define KC     200
#define NT     26            // n-tiles of 8 -> KPAD = 208
#define KPAD   (NT * 8)
#define TILE_M 128
#define SMAX   60000
#define APITCH 72            // fp16 elems per smem row (144B, conflict-free)
#define NTS    25            // uint4 per Qc row (200 bf16)
#define TRP    101           // u32 pitch of transpose buffer (conflict-dodging)

// ---------------- scratch ----------------------------------------------------
__device__ __align__(16) __nv_bfloat16 g_Qc[(size_t)SMAX * KC + 8];

// ---------------- helpers ----------------------------------------------------
__device__ __forceinline__ uint32_t pack_h2(float a, float b) {
    __half2 t = __floats2half2_rn(a, b);   // a = low half
    return *(uint32_t*)&t;
}
__device__ __forceinline__ uint32_t pack_bf2(float a, float b) {
    __nv_bfloat162 t = __floats2bfloat162_rn(a, b);
    return *(uint32_t*)&t;
}
__device__ __forceinline__ float blo(uint32_t u) {    // low bf16 -> f32 (exact)
    return __uint_as_float(u << 16);
}
__device__ __forceinline__ float bhi(uint32_t u) {    // high bf16 -> f32 (exact)
    return __uint_as_float(u & 0xffff0000u);
}

__device__ __forceinline__ void mma_f16(float c[4], const uint32_t a[4],
                                        uint32_t b0, uint32_t b1) {
    asm volatile(
        "mma.sync.aligned.m16n8k16.row.col.f32.f16.f16.f32 "
        "{%0,%1,%2,%3}, {%4,%5,%6,%7}, {%8,%9}, {%0,%1,%2,%3};"
        : "+f"(c[0]), "+f"(c[1]), "+f"(c[2]), "+f"(c[3])
        : "r"(a[0]), "r"(a[1]), "r"(a[2]), "r"(a[3]), "r"(b0), "r"(b1));
}

__device__ __forceinline__ void ldsm_x4(uint32_t& r0, uint32_t& r1,
                                        uint32_t& r2, uint32_t& r3,
                                        uint32_t addr) {
    asm volatile("ldmatrix.sync.aligned.m8n8.x4.shared.b16 {%0,%1,%2,%3}, [%4];"
        : "=r"(r0), "=r"(r1), "=r"(r2), "=r"(r3) : "r"(addr));
}

// ---------------- K1: fused fp16-HMMA logits + softmax + point + Qc ----------
// pool holds Ah[128][72] (18432B) + Bh[208][72] (29952B) = 48384B,
// later reused as tr[128][101] u32 = 51712B.
#define POOL_SZ 51712

__global__ void __launch_bounds__(256) k1_fused(
    const float* __restrict__ Z, const float* __restrict__ S,
    const float* __restrict__ sel_mu, const float* __restrict__ spa_mu,
    float* __restrict__ out, int s, float cpoint)
{
    __shared__ float4 cfp[KPAD];                 // (p0,p1,p2, 0.5*||mu||^2)
    __shared__ float4 rcp[TILE_M];               // (s0,s1,s2, ||x||^2)
    __shared__ __align__(16) char pool[POOL_SZ]; // Ah+Bh, later tr

    __half* Ah = (__half*)pool;                          // [TILE_M][APITCH]
    __half* Bh = (__half*)(pool + TILE_M * APITCH * 2);  // [KPAD][APITCH]

    const int tid = threadIdx.x, lane = tid & 31, w = tid >> 5;
    const int g = lane >> 2, tg = lane & 3;
    const int i0 = blockIdx.x * TILE_M;

    // ---- stage B (sel_mu) as fp16 ----
    #pragma unroll
    for (int it = 0; it < (KPAD * 16) / 256; ++it) {
        const int idx = it * 256 + tid;
        const int row = idx >> 4, j4 = idx & 15;
        float4 v = make_float4(0.f, 0.f, 0.f, 0.f);
        if (row < KC) v = ((const float4*)sel_mu)[row * 16 + j4];
        uint32_t* dh = (uint32_t*)(Bh + row * APITCH + j4 * 4);
        dh[0] = pack_h2(v.x, v.y); dh[1] = pack_h2(v.z, v.w);
    }

    // ---- stage A (Z tile) as fp16 ----
    #pragma unroll
    for (int it = 0; it < (TILE_M * 16) / 256; ++it) {
        const int idx = it * 256 + tid;
        const int row = idx >> 4, j4 = idx & 15;
        const int gi = i0 + row;
        float4 v = make_float4(0.f, 0.f, 0.f, 0.f);
        if (gi < s) v = ((const float4*)Z)[(size_t)gi * 16 + j4];
        uint32_t* dh = (uint32_t*)(Ah + row * APITCH + j4 * 4);
        dh[0] = pack_h2(v.x, v.y); dh[1] = pack_h2(v.z, v.w);
    }

    // ---- per-cluster coefficients ----
    if (tid < KPAD) {
        const int k = tid;
        float4 cf = make_float4(0.f, 0.f, 0.f, 1e30f);
        if (k < KC) {
            const float a = spa_mu[3 * k], b = spa_mu[3 * k + 1], c = spa_mu[3 * k + 2];
            float mn = a * a + b * b + c * c;
            const float4* mr = (const float4*)sel_mu + (size_t)k * 16;
            #pragma unroll
            for (int j = 0; j < 16; ++j) {
                float4 m = mr[j];
                mn += m.x * m.x + m.y * m.y + m.z * m.z + m.w * m.w;
            }
            cf = make_float4(a, b, c, 0.5f * mn);
        }
        cfp[k] = cf;
    }

    // ---- per-row constants ----
    if (tid < TILE_M) {
        const int gi = i0 + tid;
        float4 rc = make_float4(0.f, 0.f, 0.f, 0.f);
        if (gi < s) {
            float zn = 0.f;
            const float4* zr = (const float4*)Z + (size_t)gi * 16;
            #pragma unroll
            for (int j = 0; j < 16; ++j) {
                float4 z = zr[j];
                zn += z.x * z.x + z.y * z.y + z.z * z.z + z.w * z.w;
            }
            rc.x = S[(size_t)3 * gi];
            rc.y = S[(size_t)3 * gi + 1];
            rc.z = S[(size_t)3 * gi + 2];
            rc.w = zn + rc.x * rc.x + rc.y * rc.y + rc.z * rc.z;
        }
        rcp[tid] = rc;
    }
    __syncthreads();

    // ---- MMA mainloop: warp owns rows w*16..w*16+15, all 26 tiles ----
    float acc[NT][4];
    #pragma unroll
    for (int t = 0; t < NT; ++t)
        acc[t][0] = acc[t][1] = acc[t][2] = acc[t][3] = 0.f;

    const int r0 = w * 16 + g;
    {
        const int rr = lane & 7, q = lane >> 3;
        const uint32_t AhS = (uint32_t)__cvta_generic_to_shared(Ah);
        const uint32_t BhS = (uint32_t)__cvta_generic_to_shared(Bh);
        const uint32_t aAddr = AhS
            + (uint32_t)((w * 16 + (q & 1) * 8 + rr) * (APITCH * 2))
            + (uint32_t)((q >> 1) * 16);
        const uint32_t bAddr = BhS
            + (uint32_t)(((q >> 1) * 8 + rr) * (APITCH * 2))
            + (uint32_t)((q & 1) * 16);

        #pragma unroll
        for (int ks = 0; ks < 4; ++ks) {
            const uint32_t kb = ks * 32;   // 16 fp16 = 32 bytes per k-step
            uint32_t a[4];
            ldsm_x4(a[0], a[1], a[2], a[3], aAddr + kb);
            #pragma unroll
            for (int u = 0; u < 13; ++u) {
                uint32_t b0, b1, b2, b3;
                ldsm_x4(b0, b1, b2, b3,
                        bAddr + (uint32_t)(u * (16 * APITCH * 2)) + kb);
                mma_f16(acc[2 * u],     a, b0, b1);
                mma_f16(acc[2 * u + 1], a, b2, b3);
            }
        }
    }

    // ---- epilogue: logits + full-warp softmax (rows r0, r0+8) ----
    const float4 rc0 = rcp[r0];
    const float4 rc1 = rcp[r0 + 8];

    float m0 = -CUDART_INF_F, m1 = -CUDART_INF_F;
    #pragma unroll
    for (int t = 0; t < NT; ++t) {
        const int cb = t * 8 + 2 * tg;
        const float4 c0 = cfp[cb];
        const float4 c1 = cfp[cb + 1];
        acc[t][0] += rc0.x * c0.x + rc0.y * c0.y + rc0.z * c0.z - c0.w;
        acc[t][1] += rc0.x * c1.x + rc0.y * c1.y + rc0.z * c1.z - c1.w;
        acc[t][2] += rc1.x * c0.x + rc1.y * c0.y + rc1.z * c0.z - c0.w;
        acc[t][3] += rc1.x * c1.x + rc1.y * c1.y + rc1.z * c1.z - c1.w;
        m0 = fmaxf(m0, fmaxf(acc[t][0], acc[t][1]));
        m1 = fmaxf(m1, fmaxf(acc[t][2], acc[t][3]));
    }
    m0 = fmaxf(m0, __shfl_xor_sync(0xffffffffu, m0, 1));
    m0 = fmaxf(m0, __shfl_xor_sync(0xffffffffu, m0, 2));
    m1 = fmaxf(m1, __shfl_xor_sync(0xffffffffu, m1, 1));
    m1 = fmaxf(m1, __shfl_xor_sync(0xffffffffu, m1, 2));

    float se0 = 0.f, sl0 = 0.f, se1 = 0.f, sl1 = 0.f;
    #pragma unroll
    for (int t = 0; t < NT; ++t) {
        float e;
        e = __expf(acc[t][0] - m0); se0 += e; sl0 += e * acc[t][0]; acc[t][0] = e;
        e = __expf(acc[t][1] - m0); se0 += e; sl0 += e * acc[t][1]; acc[t][1] = e;
        e = __expf(acc[t][2] - m1); se1 += e; sl1 += e * acc[t][2]; acc[t][2] = e;
        e = __expf(acc[t][3] - m1); se1 += e; sl1 += e * acc[t][3]; acc[t][3] = e;
    }
    se0 += __shfl_xor_sync(0xffffffffu, se0, 1);
    se0 += __shfl_xor_sync(0xffffffffu, se0, 2);
    sl0 += __shfl_xor_sync(0xffffffffu, sl0, 1);
    sl0 += __shfl_xor_sync(0xffffffffu, sl0, 2);
    se1 += __shfl_xor_sync(0xffffffffu, se1, 1);
    se1 += __shfl_xor_sync(0xffffffffu, se1, 2);
    sl1 += __shfl_xor_sync(0xffffffffu, sl1, 1);
    sl1 += __shfl_xor_sync(0xffffffffu, sl1, 2);

    const float inv0 = 1.0f / se0, inv1 = 1.0f / se1;
    const int gr0 = i0 + r0, gr1 = gr0 + 8;
    if (tg == 0) {
        if (gr0 < s) out[gr0] = 0.5f * rc0.w + cpoint - sl0 * inv0;
        if (gr1 < s) out[gr1] = 0.5f * rc1.w + cpoint - sl1 * inv1;
    }

    __syncthreads();    // all ldsm reads done -> pool reusable as tr

    // ---- clipped Q -> smem transpose buffer (rows r0, r0+8) ----
    uint32_t* tr = (uint32_t*)pool;              // [TILE_M][TRP] u32 (bf16x2)
    #pragma unroll
    for (int t = 0; t < NTS; ++t) {              // tiles 0..24 (cols < 200)
        const int c = 4 * t + tg;                // u32 column 0..99
        float qa = fminf(fmaxf(acc[t][0] * inv0, 1e-6f), 1.0f - 1e-6f);
        float qb = fminf(fmaxf(acc[t][1] * inv0, 1e-6f), 1.0f - 1e-6f);
        float qc = fminf(fmaxf(acc[t][2] * inv1, 1e-6f), 1.0f - 1e-6f);
        float qd = fminf(fmaxf(acc[t][3] * inv1, 1e-6f), 1.0f - 1e-6f);
        tr[r0 * TRP + c]       = pack_bf2(qa, qb);
        tr[(r0 + 8) * TRP + c] = pack_bf2(qc, qd);
    }
    __syncthreads();

    // ---- coalesced store: each warp writes 16 full rows ----
    {
        uint32_t* __restrict__ qg = (uint32_t*)g_Qc;   // 100 u32 per row
        #pragma unroll
        for (int rr = 0; rr < 16; ++rr) {
            const int row = w * 16 + rr;
            const int gr = i0 + row;
            if (gr >= s) break;
            const uint32_t* src = tr + row * TRP;
            uint32_t* dst = qg + (size_t)gr * 100;
            dst[lane]      = src[lane];
            dst[lane + 32] = src[lane + 32];
            dst[lane + 64] = src[lane + 64];
            if (lane < 4) dst[lane + 96] = src[lane + 96];
        }
    }
}

// ---------------- K2: doublet energy (R12 shape + smem-staged D) -------------
__global__ void __launch_bounds__(256) k2_doublet(float* __restrict__ out,
                                                  const void* __restrict__ Dv,
                                                  int s, int n)
{
    __shared__ __align__(16) char sD[8 * 16 * 8];   // D slice: 8 pts x n<=16 x 8B

    const int tid = threadIdx.x, lane = tid & 31, w = tid >> 5;

    // dtype probe: true int64 ids are all in [0, s); int32 data read as int64
    // packs two ids -> almost surely out of range somewhere in 32 words.
    const long long probe = ((const long long*)Dv)[lane];
    const bool ok = (probe >= 0) && (probe < (long long)s);
    const bool is64 = (__ballot_sync(0xffffffffu, ok) == 0xffffffffu);

    const bool useSmem = (n <= 16);
    const int esz = is64 ? 8 : 4;

    // ---- cooperative stage of this block's D indices (one coalesced load) ----
    if (useSmem) {
        const int nbytes = 8 * n * esz;                       // 4B-divisible
        const size_t base = (size_t)blockIdx.x * nbytes;
        const size_t total = (size_t)s * n * esz;
        const char* Db = (const char*)Dv;
        for (int o = tid * 4; o < nbytes; o += 256 * 4) {
            uint32_t v = 0;
            if (base + o + 4 <= total) v = *(const uint32_t*)(Db + base + o);
            *(uint32_t*)(sD + o) = v;
        }
    }
    __syncthreads();

    const int i = blockIdx.x * 8 + w;
    if (i >= s) return;

    const uint4* __restrict__ Q4 = (const uint4*)g_Qc;  // row = 25 uint4
    const uint4 zero4 = make_uint4(0, 0, 0, 0);
    const unsigned ubase = (unsigned)i * NTS + (unsigned)lane;
    const uint4 ov = (lane < NTS) ? Q4[ubase] : zero4;
    float of[8];
    of[0] = blo(ov.x); of[1] = bhi(ov.x);
    of[2] = blo(ov.y); of[3] = bhi(ov.y);
    of[4] = blo(ov.z); of[5] = bhi(ov.z);
    of[6] = blo(ov.w); of[7] = bhi(ov.w);

    float doublet = 0.f;
    for (int base = 0; base < n; base += 6) {
        float acc[6]; int val[6];
        #pragma unroll
        for (int nb = 0; nb < 6; ++nb) {
            acc[nb] = 1.f; val[nb] = 0;
            const int q = base + nb;
            if (q < n) {
                long long d;
                if (useSmem) {
                    d = is64 ? ((const long long*)sD)[w * n + q]
                             : (long long)((const int*)sD)[w * n + q];
                } else {
                    d = is64 ? ((const long long*)Dv)[(size_t)i * n + q]
                             : (long long)((const int*)Dv)[(size_t)i * n + q];
                }
                val[nb] = (d >= 0 && d < s) ? 1 : 0;
                const unsigned ridx = (unsigned)(val[nb] ? (int)d : i) * NTS
                                    + (unsigned)lane;
                const uint4 nv = (lane < NTS) ? Q4[ridx] : zero4;
                float a;
                a = of[0] * blo(nv.x);
                a = fmaf(of[1], bhi(nv.x), a);
                a = fmaf(of[2], blo(nv.y), a);
                a = fmaf(of[3], bhi(nv.y), a);
                a = fmaf(of[4], blo(nv.z), a);
                a = fmaf(of[5], bhi(nv.z), a);
                a = fmaf(of[6], blo(nv.w), a);
                a = fmaf(of[7], bhi(nv.w), a);
                acc[nb] = a;
            }
        }
        #pragma unroll
        for (int off = 16; off; off >>= 1) {
            #pragma unroll
            for (int nb = 0; nb < 6; ++nb)
                acc[nb] += __shfl_xor_sync(0xffffffffu, acc[nb], off);
        }
        #pragma unroll
        for (int nb = 0; nb < 6; ++nb)
            if (!val[nb]) acc[nb] = 1.0f;
        doublet -= __logf(acc[0] * acc[1]) + __logf(acc[2] * acc[3])
                 + __logf(acc[4] * acc[5]);
    }
    if (lane == 0) out[i] += doublet;
}

// ---------------- launch -----------------------------------------------------
extern "C" void kernel_launch(void* const* d_in, const int* in_sizes, int n_in,
                              void* d_out, int out_size)
{
    const float* Z      = (const float*)d_in[0];
    const float* S      = (const float*)d_in[1];
    const void*  D      = d_in[2];
    const float* sel_mu = (const float*)d_in[3];
    const float* spa_mu = (const float*)d_in[4];
    float* out = (float*)d_out;

    const int s  = in_sizes[1] / 3;
    const int dz = in_sizes[0] / s;
    const int n  = in_sizes[2] / s;
    const float cpoint = 0.5f * (float)(dz + 3) * 1.8378770664093453f;

    k1_fused<<<(s + TILE_M - 1) / TILE_M, 256>>>(
        Z, S, sel_mu, spa_mu, out, s, cpoint);
    k2_doublet<<<(s + 7) / 8, 256>>>(out, D, s, n);
}

// round 16
// speedup vs baseline: 1.4913x; 1.0267x over previous
#include <cuda_runtime.h>
#include <cuda_fp16.h>
#include <cuda_bf16.h>
#include <math_constants.h>
#include <cstdint>

#define KC     200
#define NT     25            // n-tiles of 8 = exactly 200 cols
#define TILE_M 128
#define SMAX   60000
#define APITCH 72            // fp16 elems per smem row (144B, conflict-free)
#define NTS    25            // uint4 per Qc row (200 bf16)
#define TRP    104           // u32 pitch of transpose buffer (16B-aligned rows)
#define LOG2E  1.4426950408889634f
#define LN2    0.6931471805599453f

// ---------------- scratch ----------------------------------------------------
__device__ __align__(16) __nv_bfloat16 g_Qc[(size_t)SMAX * KC + 8];

// ---------------- helpers ----------------------------------------------------
__device__ __forceinline__ uint32_t pack_h2(float a, float b) {
    __half2 t = __floats2half2_rn(a, b);   // a = low half
    return *(uint32_t*)&t;
}
__device__ __forceinline__ uint32_t pack_bf2(float a, float b) {
    __nv_bfloat162 t = __floats2bfloat162_rn(a, b);
    return *(uint32_t*)&t;
}
__device__ __forceinline__ float blo(uint32_t u) {    // low bf16 -> f32 (exact)
    return __uint_as_float(u << 16);
}
__device__ __forceinline__ float bhi(uint32_t u) {    // high bf16 -> f32 (exact)
    return __uint_as_float(u & 0xffff0000u);
}
__device__ __forceinline__ float ex2(float x) {       // 1 MUFU, no FMUL
    float r;
    asm("ex2.approx.f32 %0, %1;" : "=f"(r) : "f"(x));
    return r;
}

__device__ __forceinline__ void mma_f16(float c[4], const uint32_t a[4],
                                        uint32_t b0, uint32_t b1) {
    asm volatile(
        "mma.sync.aligned.m16n8k16.row.col.f32.f16.f16.f32 "
        "{%0,%1,%2,%3}, {%4,%5,%6,%7}, {%8,%9}, {%0,%1,%2,%3};"
        : "+f"(c[0]), "+f"(c[1]), "+f"(c[2]), "+f"(c[3])
        : "r"(a[0]), "r"(a[1]), "r"(a[2]), "r"(a[3]), "r"(b0), "r"(b1));
}

__device__ __forceinline__ void ldsm_x4(uint32_t& r0, uint32_t& r1,
                                        uint32_t& r2, uint32_t& r3,
                                        uint32_t addr) {
    asm volatile("ldmatrix.sync.aligned.m8n8.x4.shared.b16 {%0,%1,%2,%3}, [%4];"
        : "=r"(r0), "=r"(r1), "=r"(r2), "=r"(r3) : "r"(addr));
}
__device__ __forceinline__ void ldsm_x2(uint32_t& r0, uint32_t& r1,
                                        uint32_t addr) {
    asm volatile("ldmatrix.sync.aligned.m8n8.x2.shared.b16 {%0,%1}, [%2];"
        : "=r"(r0), "=r"(r1) : "r"(addr));
}

// ---------------- K1: fused fp16-HMMA logits + softmax + point + Qc ----------
// pool holds Ah[128][72] (18432B) + Bh[200][72] (28800B) = 47232B,
// later reused as tr[128][104] u32 = 53248B.
#define POOL_SZ 53248

__global__ void __launch_bounds__(256) k1_fused(
    const float* __restrict__ Z, const float* __restrict__ S,
    const float* __restrict__ sel_mu, const float* __restrict__ spa_mu,
    float* __restrict__ out, int s, float cpoint)
{
    __shared__ float4 cfp[KC];                   // (p0,p1,p2, .5||mu||^2)*log2e
    __shared__ float4 rcp[TILE_M];               // (s0,s1,s2, ||x||^2)
    __shared__ __align__(16) char pool[POOL_SZ]; // Ah+Bh, later tr

    __half* Ah = (__half*)pool;                          // [TILE_M][APITCH]
    __half* Bh = (__half*)(pool + TILE_M * APITCH * 2);  // [KC][APITCH]

    const int tid = threadIdx.x, lane = tid & 31, w = tid >> 5;
    const int g = lane >> 2, tg = lane & 3;
    const int i0 = blockIdx.x * TILE_M;

    // ---- stage B (sel_mu * log2e) as fp16 ----
    #pragma unroll
    for (int it = 0; it < 13; ++it) {
        const int idx = it * 256 + tid;
        if (idx < KC * 16) {
            const int row = idx >> 4, j4 = idx & 15;
            float4 v = ((const float4*)sel_mu)[row * 16 + j4];
            uint32_t* dh = (uint32_t*)(Bh + row * APITCH + j4 * 4);
            dh[0] = pack_h2(v.x * LOG2E, v.y * LOG2E);
            dh[1] = pack_h2(v.z * LOG2E, v.w * LOG2E);
        }
    }

    // ---- stage A (Z tile) as fp16 ----
    #pragma unroll
    for (int it = 0; it < (TILE_M * 16) / 256; ++it) {
        const int idx = it * 256 + tid;
        const int row = idx >> 4, j4 = idx & 15;
        const int gi = i0 + row;
        float4 v = make_float4(0.f, 0.f, 0.f, 0.f);
        if (gi < s) v = ((const float4*)Z)[(size_t)gi * 16 + j4];
        uint32_t* dh = (uint32_t*)(Ah + row * APITCH + j4 * 4);
        dh[0] = pack_h2(v.x, v.y); dh[1] = pack_h2(v.z, v.w);
    }

    // ---- per-cluster coefficients (pre-scaled by log2e) ----
    if (tid < KC) {
        const int k = tid;
        const float a = spa_mu[3 * k], b = spa_mu[3 * k + 1], c = spa_mu[3 * k + 2];
        float mn = a * a + b * b + c * c;
        const float4* mr = (const float4*)sel_mu + (size_t)k * 16;
        #pragma unroll
        for (int j = 0; j < 16; ++j) {
            float4 m = mr[j];
            mn += m.x * m.x + m.y * m.y + m.z * m.z + m.w * m.w;
        }
        cfp[k] = make_float4(a * LOG2E, b * LOG2E, c * LOG2E,
                             0.5f * mn * LOG2E);
    }

    // ---- per-row constants ----
    if (tid < TILE_M) {
        const int gi = i0 + tid;
        float4 rc = make_float4(0.f, 0.f, 0.f, 0.f);
        if (gi < s) {
            float zn = 0.f;
            const float4* zr = (const float4*)Z + (size_t)gi * 16;
            #pragma unroll
            for (int j = 0; j < 16; ++j) {
                float4 z = zr[j];
                zn += z.x * z.x + z.y * z.y + z.z * z.z + z.w * z.w;
            }
            rc.x = S[(size_t)3 * gi];
            rc.y = S[(size_t)3 * gi + 1];
            rc.z = S[(size_t)3 * gi + 2];
            rc.w = zn + rc.x * rc.x + rc.y * rc.y + rc.z * rc.z;
        }
        rcp[tid] = rc;
    }
    __syncthreads();

    // ---- MMA mainloop: 12 tile-pairs (x4) + 1 single tile (x2) ----
    float acc[NT][4];
    #pragma unroll
    for (int t = 0; t < NT; ++t)
        acc[t][0] = acc[t][1] = acc[t][2] = acc[t][3] = 0.f;

    const int r0 = w * 16 + g;
    {
        const int rr = lane & 7, q = lane >> 3;
        const uint32_t AhS = (uint32_t)__cvta_generic_to_shared(Ah);
        const uint32_t BhS = (uint32_t)__cvta_generic_to_shared(Bh);
        const uint32_t aAddr = AhS
            + (uint32_t)((w * 16 + (q & 1) * 8 + rr) * (APITCH * 2))
            + (uint32_t)((q >> 1) * 16);
        const uint32_t bAddr = BhS
            + (uint32_t)(((q >> 1) * 8 + rr) * (APITCH * 2))
            + (uint32_t)((q & 1) * 16);
        const uint32_t bAddr2 = BhS
            + (uint32_t)((24 * 8 + rr) * (APITCH * 2))
            + (uint32_t)((q & 1) * 16);

        #pragma unroll
        for (int ks = 0; ks < 4; ++ks) {
            const uint32_t kb = ks * 32;   // 16 fp16 = 32 bytes per k-step
            uint32_t a[4];
            ldsm_x4(a[0], a[1], a[2], a[3], aAddr + kb);
            #pragma unroll
            for (int u = 0; u < 12; ++u) {
                uint32_t b0, b1, b2, b3;
                ldsm_x4(b0, b1, b2, b3,
                        bAddr + (uint32_t)(u * (16 * APITCH * 2)) + kb);
                mma_f16(acc[2 * u],     a, b0, b1);
                mma_f16(acc[2 * u + 1], a, b2, b3);
            }
            uint32_t c0, c1;
            ldsm_x2(c0, c1, bAddr2 + kb);
            mma_f16(acc[24], a, c0, c1);
        }
    }

    // ---- epilogue: scaled logits + full-warp softmax (rows r0, r0+8) ----
    const float4 rc0 = rcp[r0];
    const float4 rc1 = rcp[r0 + 8];

    float m0 = -CUDART_INF_F, m1 = -CUDART_INF_F;
    #pragma unroll
    for (int t = 0; t < NT; ++t) {
        const int cb = t * 8 + 2 * tg;
        const float4 c0 = cfp[cb];
        const float4 c1 = cfp[cb + 1];
        acc[t][0] += rc0.x * c0.x + rc0.y * c0.y + rc0.z * c0.z - c0.w;
        acc[t][1] += rc0.x * c1.x + rc0.y * c1.y + rc0.z * c1.z - c1.w;
        acc[t][2] += rc1.x * c0.x + rc1.y * c0.y + rc1.z * c0.z - c0.w;
        acc[t][3] += rc1.x * c1.x + rc1.y * c1.y + rc1.z * c1.z - c1.w;
        m0 = fmaxf(m0, fmaxf(acc[t][0], acc[t][1]));
        m1 = fmaxf(m1, fmaxf(acc[t][2], acc[t][3]));
    }
    m0 = fmaxf(m0, __shfl_xor_sync(0xffffffffu, m0, 1));
    m0 = fmaxf(m0, __shfl_xor_sync(0xffffffffu, m0, 2));
    m1 = fmaxf(m1, __shfl_xor_sync(0xffffffffu, m1, 1));
    m1 = fmaxf(m1, __shfl_xor_sync(0xffffffffu, m1, 2));

    float se0 = 0.f, sl0 = 0.f, se1 = 0.f, sl1 = 0.f;
    #pragma unroll
    for (int t = 0; t < NT; ++t) {
        float e;
        e = ex2(acc[t][0] - m0); se0 += e; sl0 += e * acc[t][0]; acc[t][0] = e;
        e = ex2(acc[t][1] - m0); se0 += e; sl0 += e * acc[t][1]; acc[t][1] = e;
        e = ex2(acc[t][2] - m1); se1 += e; sl1 += e * acc[t][2]; acc[t][2] = e;
        e = ex2(acc[t][3] - m1); se1 += e; sl1 += e * acc[t][3]; acc[t][3] = e;
    }
    se0 += __shfl_xor_sync(0xffffffffu, se0, 1);
    se0 += __shfl_xor_sync(0xffffffffu, se0, 2);
    sl0 += __shfl_xor_sync(0xffffffffu, sl0, 1);
    sl0 += __shfl_xor_sync(0xffffffffu, sl0, 2);
    se1 += __shfl_xor_sync(0xffffffffu, se1, 1);
    se1 += __shfl_xor_sync(0xffffffffu, se1, 2);
    sl1 += __shfl_xor_sync(0xffffffffu, sl1, 1);
    sl1 += __shfl_xor_sync(0xffffffffu, sl1, 2);

    const float inv0 = 1.0f / se0, inv1 = 1.0f / se1;
    const int gr0 = i0 + r0, gr1 = gr0 + 8;
    if (tg == 0) {
        // sl is in log2 units -> multiply by ln2 once
        if (gr0 < s) out[gr0] = 0.5f * rc0.w + cpoint - sl0 * inv0 * LN2;
        if (gr1 < s) out[gr1] = 0.5f * rc1.w + cpoint - sl1 * inv1 * LN2;
    }

    __syncthreads();    // all ldsm reads done -> pool reusable as tr

    // ---- clipped Q -> smem transpose buffer (rows r0, r0+8) ----
    uint32_t* tr = (uint32_t*)pool;              // [TILE_M][TRP] u32 (bf16x2)
    #pragma unroll
    for (int t = 0; t < NT; ++t) {
        const int c = 4 * t + tg;                // u32 column 0..99
        float qa = fminf(fmaxf(acc[t][0] * inv0, 1e-6f), 1.0f - 1e-6f);
        float qb = fminf(fmaxf(acc[t][1] * inv0, 1e-6f), 1.0f - 1e-6f);
        float qc = fminf(fmaxf(acc[t][2] * inv1, 1e-6f), 1.0f - 1e-6f);
        float qd = fminf(fmaxf(acc[t][3] * inv1, 1e-6f), 1.0f - 1e-6f);
        tr[r0 * TRP + c]       = pack_bf2(qa, qb);
        tr[(r0 + 8) * TRP + c] = pack_bf2(qc, qd);
    }
    __syncthreads();

    // ---- coalesced uint4 store: each warp writes 16 full rows ----
    {
        uint4* __restrict__ qg = (uint4*)g_Qc;         // 25 uint4 per row
        #pragma unroll
        for (int rr = 0; rr < 16; ++rr) {
            const int row = w * 16 + rr;
            const int gr = i0 + row;
            if (gr >= s) break;
            if (lane < NTS) {
                const uint4 v = ((const uint4*)(tr + row * TRP))[lane];
                qg[(size_t)gr * NTS + lane] = v;
            }
        }
    }
}

// ---------------- K2: doublet energy (byte-exact R12 shape) ------------------
__global__ void __launch_bounds__(256) k2_doublet(float* __restrict__ out,
                                                  const void* __restrict__ Dv,
                                                  int s, int n)
{
    const int t = threadIdx.x, lane = t & 31, w = t >> 5;

    // dtype probe: true int64 ids are all in [0, s); int32 data read as int64
    // packs two ids -> almost surely out of range somewhere in 32 words.
    const long long probe = ((const long long*)Dv)[lane];
    const bool ok = (probe >= 0) && (probe < (long long)s);
    const bool is64 = (__ballot_sync(0xffffffffu, ok) == 0xffffffffu);

    const int i = blockIdx.x * 8 + w;
    if (i >= s) return;

    const uint4* __restrict__ Q4 = (const uint4*)g_Qc;  // row = 25 uint4
    const uint4 zero4 = make_uint4(0, 0, 0, 0);
    const unsigned ubase = (unsigned)i * NTS + (unsigned)lane;
    const uint4 ov = (lane < NTS) ? Q4[ubase] : zero4;
    float of[8];
    of[0] = blo(ov.x); of[1] = bhi(ov.x);
    of[2] = blo(ov.y); of[3] = bhi(ov.y);
    of[4] = blo(ov.z); of[5] = bhi(ov.z);
    of[6] = blo(ov.w); of[7] = bhi(ov.w);

    float doublet = 0.f;
    for (int base = 0; base < n; base += 6) {
        float acc[6]; int val[6];
        #pragma unroll
        for (int nb = 0; nb < 6; ++nb) {
            acc[nb] = 1.f; val[nb] = 0;
            const int q = base + nb;
            if (q < n) {
                long long d = is64 ? ((const long long*)Dv)[(unsigned)i * n + q]
                                   : (long long)((const int*)Dv)[(unsigned)i * n + q];
                val[nb] = (d >= 0 && d < s) ? 1 : 0;
                const unsigned ridx = (unsigned)(val[nb] ? (int)d : i) * NTS
                                    + (unsigned)lane;
                const uint4 nv = (lane < NTS) ? Q4[ridx] : zero4;
                float a;
                a = of[0] * blo(nv.x);
                a = fmaf(of[1], bhi(nv.x), a);
                a = fmaf(of[2], blo(nv.y), a);
                a = fmaf(of[3], bhi(nv.y), a);
                a = fmaf(of[4], blo(nv.z), a);
                a = fmaf(of[5], bhi(nv.z), a);
                a = fmaf(of[6], blo(nv.w), a);
                a = fmaf(of[7], bhi(nv.w), a);
                acc[nb] = a;
            }
        }
        #pragma unroll
        for (int off = 16; off; off >>= 1) {
            #pragma unroll
            for (int nb = 0; nb < 6; ++nb)
                acc[nb] += __shfl_xor_sync(0xffffffffu, acc[nb], off);
        }
        #pragma unroll
        for (int nb = 0; nb < 6; ++nb)
            if (!val[nb]) acc[nb] = 1.0f;
        doublet -= __logf(acc[0] * acc[1]) + __logf(acc[2] * acc[3])
                 + __logf(acc[4] * acc[5]);
    }
    if (lane == 0) out[i] += doublet;
}

// ---------------- launch -----------------------------------------------------
extern "C" void kernel_launch(void* const* d_in, const int* in_sizes, int n_in,
                              void* d_out, int out_size)
{
    const float* Z      = (const float*)d_in[0];
    const float* S      = (const float*)d_in[1];
    const void*  D      = d_in[2];
    const float* sel_mu = (const float*)d_in[3];
    const float* spa_mu = (const float*)d_in[4];
    float* out = (float*)d_out;

    const int s  = in_sizes[1] / 3;
    const int dz = in_sizes[0] / s;
    const int n  = in_sizes[2] / s;
    const float cpoint = 0.5f * (float)(dz + 3) * 1.8378770664093453f;

    k1_fused<<<(s + TILE_M - 1) / TILE_M, 256>>>(
        Z, S, sel_mu, spa_mu, out, s, cpoint);
    k2_doublet<<<(s + 7) / 8, 256>>>(out, D, s, n);
}